// round 17
// baseline (speedup 1.0000x reference)
#include <cuda_runtime.h>

#define BB 64
#define II 512
#define HH 1024
#define NCHUNK 64              // h-dimension split for rec items
#define HCHUNK (HH / NCHUNK)   // 16
#define BTILE 8                // batches per item in rec kernel
#define BGROUPS (BB / BTILE)   // 8
#define NITEMS (NCHUNK * BGROUPS)   // 512 work items
#define PERSIST_BLOCKS 296     // 148 SMs x 2 blocks (lb(256,2) slots)
#define CROWS 8                // (b,h) rows per block in hebb update
#define WSEG 16                // K-segments for h_pre@weight (K=64 each)
#define XSEG 8                 // K-segments for x@fc_w^T   (K=64 each)
#define CLIPV 2.0f
#define LN_EPS 1e-5f

// Scratch (no allocations allowed -> __device__ globals)
// Invariants at kernel_launch entry (zero at module load, restored each run):
//   g_pre == 0   (ln_mod re-zeroes after reading)
//   g_ctr == 0, g_done == 0  (last rec block resets both)
__device__ float g_pre[BB][HH];    // atomic accumulator (rec + both gemms)
__device__ float g_etah[BB][HH];   // eta * h_post
__device__ int   g_ctr;            // rec work-item counter
__device__ int   g_done;           // rec finished-block counter

__device__ __forceinline__ float4 ldcs4(const float4* p)
{
    float4 v;
    asm volatile("ld.global.cs.v4.f32 {%0,%1,%2,%3}, [%4];"
                 : "=f"(v.x), "=f"(v.y), "=f"(v.z), "=f"(v.w) : "l"(p));
    return v;
}

__device__ __forceinline__ void stcs4(float4* p, float4 v)
{
    asm volatile("st.global.cs.v4.f32 [%0], {%1,%2,%3,%4};"
                 :: "l"(p), "f"(v.x), "f"(v.y), "f"(v.z), "f"(v.w));
}

// ---------------------------------------------------------------------------
// Kernel A: rec hebb contribution -> g_pre, PERSISTENT + work-stealing.
// item = (chunk, bg): g_pre[b][k] += sum_{h in 16-chunk} h_pre*alpha*hebb.
// R17 theory: static 256-block grid on 296 slots lost ~14% to wave
// quantization (108 SMs ran 2 blocks, 40 ran 1). Persistent 296 blocks pull
// 512 fine-grain items (~0.9us each) off g_ctr -> makespan = ideal + 1 item.
// LTS bytes unchanged: 268 hebb + 32 alpha + 16 atomics ~ 316 MB.
// ---------------------------------------------------------------------------
__global__ __launch_bounds__(256, 2) void rec_partial_kernel(
    const float* __restrict__ h_pre, const float* __restrict__ hebb,
    const float* __restrict__ alpha)
{
    const int tid = threadIdx.x;
    __shared__ float hp[BTILE][HCHUNK];
    __shared__ int s_item;

    const float4* a4 = reinterpret_cast<const float4*>(alpha);
    const float4* e4 = reinterpret_cast<const float4*>(hebb);

    for (;;) {
        __syncthreads();                    // protect hp/s_item from prev item
        if (tid == 0) s_item = atomicAdd(&g_ctr, 1);
        __syncthreads();
        const int item = s_item;
        if (item >= NITEMS) break;

        const int chunk = item >> 3;        // 0..63
        const int bg    = item & 7;         // 0..7
        const int b0    = bg * BTILE;
        const int h0    = chunk * HCHUNK;

        if (tid < BTILE * HCHUNK) {         // 128 threads load h_pre tile
            int j  = tid >> 4;              // 0..7
            int hh = tid & 15;              // 0..15
            hp[j][hh] = h_pre[(b0 + j) * HH + h0 + hh];
        }
        __syncthreads();

        float4 acc[BTILE];
#pragma unroll
        for (int j = 0; j < BTILE; ++j) acc[j] = make_float4(0.f, 0.f, 0.f, 0.f);

        const float4* pj[BTILE];
#pragma unroll
        for (int j = 0; j < BTILE; ++j)
            pj[j] = e4 + ((b0 + j) * HH + h0) * (HH / 4) + tid;

#pragma unroll 2
        for (int hi = 0; hi < HCHUNK; ++hi) {
            const int h = h0 + hi;
            const float4 a = a4[h * (HH / 4) + tid];
            float4 e[BTILE];
#pragma unroll
            for (int j = 0; j < BTILE; ++j)
                e[j] = ldcs4(pj[j] + hi * (HH / 4));
#pragma unroll
            for (int j = 0; j < BTILE; ++j) {
                const float s = hp[j][hi];
                acc[j].x = fmaf(s * a.x, e[j].x, acc[j].x);
                acc[j].y = fmaf(s * a.y, e[j].y, acc[j].y);
                acc[j].z = fmaf(s * a.z, e[j].z, acc[j].z);
                acc[j].w = fmaf(s * a.w, e[j].w, acc[j].w);
            }
        }

#pragma unroll
        for (int j = 0; j < BTILE; ++j)
            atomicAdd(reinterpret_cast<float4*>(&g_pre[b0 + j][0]) + tid, acc[j]);
    }

    // last finishing block resets the counters for the next graph replay
    if (tid == 0) {
        int d = atomicAdd(&g_done, 1);
        if (d == gridDim.x - 1) { g_ctr = 0; g_done = 0; }
    }
}

// ---------------------------------------------------------------------------
// Kernel G: BOTH small GEMMs in one launch, K=64/block (2 smem steps).
// blockIdx.y = seg: 0..WSEG-1     -> g_pre += h_pre[:, seg*64:+64] @ weight
//              WSEG..WSEG+XSEG-1  -> g_pre += x[:, s*64:+64] @ fc_w^T
// Register-tiled 64b x 64k, 4x4 out/thread, atomic float4 epilogue.
// Grid 16 x 24 = 384 blocks. (R16-measured OK.)
// ---------------------------------------------------------------------------
__global__ __launch_bounds__(256) void gemm_all_kernel(
    const float* __restrict__ h_pre, const float* __restrict__ weight,
    const float* __restrict__ x, const float* __restrict__ fc_w)
{
    __shared__ float asm_[64][33];  // [b][red-step]
    __shared__ float bsm[64][65];   // weight: [h-step][k] (32x65 used); x: [k][i-step] (64x33 used)
    const int k0  = blockIdx.x * 64;
    const int seg = blockIdx.y;
    const int tid = threadIdx.x;
    const int tx  = tid & 15;       // k quad
    const int ty  = tid >> 4;       // b quad

    float acc[4][4];
#pragma unroll
    for (int i = 0; i < 4; ++i)
#pragma unroll
        for (int j = 0; j < 4; ++j) acc[i][j] = 0.f;

    if (seg < WSEG) {
        for (int step = 0; step < 2; ++step) {
            const int hh0 = seg * 64 + step * 32;
            __syncthreads();
#pragma unroll
            for (int r = 0; r < 8; ++r) {
                int idx = tid + r * 256;
                int row = idx >> 5;     // 0..63 (b)
                int col = idx & 31;     // 0..31 (h)
                asm_[row][col] = h_pre[row * HH + hh0 + col];
            }
#pragma unroll
            for (int r = 0; r < 8; ++r) {
                int idx = tid + r * 256;
                int row = idx >> 6;     // 0..31 (h)
                int col = idx & 63;     // 0..63 (k)
                bsm[row][col] = weight[(hh0 + row) * HH + k0 + col];
            }
            __syncthreads();
#pragma unroll
            for (int ii = 0; ii < 32; ++ii) {
                float xv[4], wv[4];
#pragma unroll
                for (int q = 0; q < 4; ++q) { xv[q] = asm_[ty * 4 + q][ii]; wv[q] = bsm[ii][tx * 4 + q]; }
#pragma unroll
                for (int bi = 0; bi < 4; ++bi)
#pragma unroll
                    for (int ki = 0; ki < 4; ++ki)
                        acc[bi][ki] = fmaf(xv[bi], wv[ki], acc[bi][ki]);
            }
        }
    } else {
        const int xs = seg - WSEG;
        float (*wsm)[33] = reinterpret_cast<float (*)[33]>(&bsm[0][0]); // 64x33 view
        for (int step = 0; step < 2; ++step) {
            const int ii0 = xs * 64 + step * 32;
            __syncthreads();
#pragma unroll
            for (int r = 0; r < 8; ++r) {
                int idx = tid + r * 256;
                int row = idx >> 5;     // 0..63
                int col = idx & 31;     // 0..31
                asm_[row][col] = x[row * II + ii0 + col];
                wsm[row][col]  = fc_w[(k0 + row) * II + ii0 + col];
            }
            __syncthreads();
#pragma unroll
            for (int ii = 0; ii < 32; ++ii) {
                float xv[4], wv[4];
#pragma unroll
                for (int q = 0; q < 4; ++q) { xv[q] = asm_[ty * 4 + q][ii]; wv[q] = wsm[tx * 4 + q][ii]; }
#pragma unroll
                for (int bi = 0; bi < 4; ++bi)
#pragma unroll
                    for (int ki = 0; ki < 4; ++ki)
                        acc[bi][ki] = fmaf(xv[bi], wv[ki], acc[bi][ki]);
            }
        }
    }

#pragma unroll
    for (int bi = 0; bi < 4; ++bi) {
        float4 v = make_float4(acc[bi][0], acc[bi][1], acc[bi][2], acc[bi][3]);
        atomicAdd(reinterpret_cast<float4*>(&g_pre[ty * 4 + bi][k0 + tx * 4]), v);
    }
}

// ---------------------------------------------------------------------------
// Kernel B2: per-batch LN + tanh + m + etah.
// Reads g_pre (+fc_b), then ZEROES g_pre for the next replay.
// ---------------------------------------------------------------------------
__device__ __forceinline__ float block_reduce_sum(float v, float* sred, int tid)
{
#pragma unroll
    for (int o = 16; o > 0; o >>= 1) v += __shfl_down_sync(0xffffffffu, v, o);
    if ((tid & 31) == 0) sred[tid >> 5] = v;
    __syncthreads();
    if (tid < 8) {
        float x = sred[tid];
#pragma unroll
        for (int o = 4; o > 0; o >>= 1) x += __shfl_down_sync(0xffu, x, o);
        if (tid == 0) sred[0] = x;
    }
    __syncthreads();
    float r = sred[0];
    __syncthreads();   // protect sred for next reduction
    return r;
}

__global__ __launch_bounds__(256) void ln_mod_kernel(
    const float* __restrict__ fc_b,
    const float* __restrict__ ln_g,  const float* __restrict__ ln_b,
    const float* __restrict__ mod_w, const float* __restrict__ mod_b,
    const float* __restrict__ modf_w, const float* __restrict__ modf_b,
    float* __restrict__ out_hpost, float* __restrict__ out_m)
{
    const int b   = blockIdx.x;
    const int tid = threadIdx.x;
    __shared__ float sred[8];
    __shared__ float sm;

    float4 v  = reinterpret_cast<const float4*>(&g_pre[b][0])[tid];
    float4 fb = reinterpret_cast<const float4*>(fc_b)[tid];
    v.x += fb.x; v.y += fb.y; v.z += fb.z; v.w += fb.w;

    // restore g_pre = 0 for the next replay
    reinterpret_cast<float4*>(&g_pre[b][0])[tid] = make_float4(0.f, 0.f, 0.f, 0.f);

    float s  = v.x + v.y + v.z + v.w;
    float s2 = v.x * v.x + v.y * v.y + v.z * v.z + v.w * v.w;
    s  = block_reduce_sum(s,  sred, tid);
    s2 = block_reduce_sum(s2, sred, tid);
    const float mu   = s / (float)HH;
    const float var  = s2 / (float)HH - mu * mu;
    const float rstd = rsqrtf(var + LN_EPS);

    float4 g  = reinterpret_cast<const float4*>(ln_g)[tid];
    float4 be = reinterpret_cast<const float4*>(ln_b)[tid];
    float4 hp;
    hp.x = tanhf((v.x - mu) * rstd * g.x + be.x);
    hp.y = tanhf((v.y - mu) * rstd * g.y + be.y);
    hp.z = tanhf((v.z - mu) * rstd * g.z + be.z);
    hp.w = tanhf((v.w - mu) * rstd * g.w + be.w);
    reinterpret_cast<float4*>(out_hpost + b * HH)[tid] = hp;

    // m = tanh(dot(h_post, mod_w) + mod_b)
    float4 mw = reinterpret_cast<const float4*>(mod_w)[tid];
    float d = hp.x * mw.x + hp.y * mw.y + hp.z * mw.z + hp.w * mw.w;
    d = block_reduce_sum(d, sred, tid);
    if (tid == 0) {
        float m = tanhf(d + mod_b[0]);
        out_m[b] = m;
        sm = m;
    }
    __syncthreads();
    const float m = sm;

    // etah[b,k] = (m*modf_w[k] + modf_b[k]) * h_post[b,k]
    float4 fw  = reinterpret_cast<const float4*>(modf_w)[tid];
    float4 fbb = reinterpret_cast<const float4*>(modf_b)[tid];
    float4 t;
    t.x = fmaf(m, fw.x, fbb.x) * hp.x;
    t.y = fmaf(m, fw.y, fbb.y) * hp.y;
    t.z = fmaf(m, fw.z, fbb.z) * hp.z;
    t.w = fmaf(m, fw.w, fbb.w) * hp.w;
    reinterpret_cast<float4*>(&g_etah[b][0])[tid] = t;
}

// ---------------------------------------------------------------------------
// Kernel C: hebb_new[b,h,k] = clip(hebb[b,h,k] + h_pre[b,h]*etah[b,k])
// Measured at ~77% of HBM spec across rounds (practical ceiling); unchanged.
// ---------------------------------------------------------------------------
__global__ __launch_bounds__(256) void hebb_update_kernel(
    const float* __restrict__ h_pre, const float* __restrict__ hebb,
    float* __restrict__ out_hebb)
{
    const int row0 = blockIdx.x * CROWS;
    const int tid  = threadIdx.x;
#pragma unroll
    for (int r = 0; r < CROWS; ++r) {
        const int bh = row0 + r;
        const int b  = bh >> 10;
        const float hpv = __ldg(&h_pre[bh]);   // h_pre[b*H + h] == h_pre[bh]
        const float4 e = ldcs4(reinterpret_cast<const float4*>(hebb) + bh * (HH / 4) + tid);
        const float4 t = reinterpret_cast<const float4*>(&g_etah[b][0])[tid];
        float4 o;
        o.x = fminf(fmaxf(fmaf(hpv, t.x, e.x), -CLIPV), CLIPV);
        o.y = fminf(fmaxf(fmaf(hpv, t.y, e.y), -CLIPV), CLIPV);
        o.z = fminf(fmaxf(fmaf(hpv, t.z, e.z), -CLIPV), CLIPV);
        o.w = fminf(fmaxf(fmaf(hpv, t.w, e.w), -CLIPV), CLIPV);
        stcs4(reinterpret_cast<float4*>(out_hebb) + bh * (HH / 4) + tid, o);
    }
}

// ---------------------------------------------------------------------------
// Launch. Inputs in metadata order:
// 0 x, 1 h_pre, 2 hebb, 3 fc_w, 4 fc_b, 5 weight, 6 alpha,
// 7 ln_g, 8 ln_b, 9 mod_w, 10 mod_b, 11 modf_w, 12 modf_b
// Output: h_post [64*1024] | m [64] | hebb_new [64*1024*1024], fp32.
// ---------------------------------------------------------------------------
extern "C" void kernel_launch(void* const* d_in, const int* in_sizes, int n_in,
                              void* d_out, int out_size)
{
    const float* x      = (const float*)d_in[0];
    const float* h_pre  = (const float*)d_in[1];
    const float* hebb   = (const float*)d_in[2];
    const float* fc_w   = (const float*)d_in[3];
    const float* fc_b   = (const float*)d_in[4];
    const float* weight = (const float*)d_in[5];
    const float* alpha  = (const float*)d_in[6];
    const float* ln_g   = (const float*)d_in[7];
    const float* ln_b   = (const float*)d_in[8];
    const float* mod_w  = (const float*)d_in[9];
    const float* mod_b  = (const float*)d_in[10];
    const float* modf_w = (const float*)d_in[11];
    const float* modf_b = (const float*)d_in[12];

    float* out       = (float*)d_out;
    float* out_hpost = out;                 // 64*1024
    float* out_m     = out + BB * HH;       // 64
    float* out_hebb  = out + BB * HH + BB;  // 64*1024*1024

    rec_partial_kernel<<<PERSIST_BLOCKS, 256>>>(h_pre, hebb, alpha);
    gemm_all_kernel<<<dim3(HH / 64, WSEG + XSEG), 256>>>(h_pre, weight, x, fc_w);
    ln_mod_kernel<<<BB, 256>>>(fc_b, ln_g, ln_b, mod_w, mod_b, modf_w, modf_b,
                               out_hpost, out_m);
    hebb_update_kernel<<<(BB * HH) / CROWS, 256>>>(h_pre, hebb, out_hebb);
}